// round 11
// baseline (speedup 1.0000x reference)
#include <cuda_runtime.h>
#include <math.h>

#define TT 1024
#define BB 16
#define SS 2
#define NN 2048
#define BN (BB * NN)     // 32768
#define LL 100
#define SLOTS 128

// vmem scratch, TILED layout: [group = bn/32][t][bn%32]  (coalesced for scan)
__device__ float g_vmem[(size_t)BN * TT];

// ---------------------------------------------------------------------------
// Phase 1: EPSP conv. Bit-exact fold (ascending spike time, per synapse, then
// v = a0 + a1). R8 structure, with the bit-transpose replaced by a warp-ballot
// transpose (~45x fewer instructions, bit-identical result).
// ---------------------------------------------------------------------------
__global__ __launch_bounds__(256) void snn_epsp_kernel(
    const float* __restrict__ spikes,   // (T, B, S, N)
    const float* __restrict__ eps)      // (S, L)
{
    __shared__ unsigned smasks[2 * TT];     // [s*TT + t], bit i = neuron n0+i
    __shared__ unsigned sW[2 * 32 * 32];    // [s*1024 + j*32 + w], bit i = t=w*32+i
    __shared__ float sk[2 * LL];
    __shared__ float stile[32 * 33];

    const int tid = threadIdx.x;
    const int warpId = tid >> 5;
    const int lane = tid & 31;
    const int b  = blockIdx.x >> 6;
    const int n0 = (blockIdx.x & 63) * 32;

    for (int i = tid; i < 2 * LL; i += 256) sk[i] = eps[i];

    // ballot spikes -> per-(s,t) neuron masks (coalesced loads)
    for (int idx = warpId; idx < 2 * TT; idx += 8) {
        const int s = idx >> 10;
        const int t = idx & (TT - 1);
        const float val = spikes[(((size_t)t * BB + b) * SS + s) * NN + n0 + lane];
        const unsigned m = __ballot_sync(0xFFFFFFFFu, val != 0.0f);
        if (lane == 0) smasks[s * TT + t] = m;
    }
    __syncthreads();

    // warp-ballot bit-transpose: tile = (s, w) of 32 times x 32 neurons
    for (int tile = warpId; tile < 64; tile += 8) {
        const int s = tile >> 5;
        const int w = tile & 31;
        const unsigned m = smasks[s * TT + w * 32 + lane];  // times w*32+lane
#pragma unroll
        for (int j = 0; j < 32; ++j) {
            const unsigned bjt = __ballot_sync(0xFFFFFFFFu, (m >> j) & 1u);
            if (lane == j) sW[s * 1024 + j * 32 + w] = bjt;
        }
    }
    __syncthreads();

    const size_t gbase = (size_t)blockIdx.x * (32 * TT);

#pragma unroll 1
    for (int c = 0; c < 32; ++c) {
        const int t = c * 32 + lane;
        const int wlo = (c * 32 >= 99) ? ((c * 32 - 99) >> 5) : 0;

#pragma unroll 1
        for (int jj = 0; jj < 4; ++jj) {
            const int j = warpId + jj * 8;
            const unsigned* W0 = &sW[j * 32];
            const unsigned* W1 = &sW[1024 + j * 32];

            float a0 = 0.0f;
#pragma unroll 1
            for (int w = wlo; w <= c; ++w) {
                unsigned mm = W0[w];                 // warp-uniform
                const int base = w << 5;
                while (mm) {
                    const int i = __ffs(mm) - 1;
                    mm &= mm - 1;
                    const int lag = t - (base + i);  // per-lane
                    if ((unsigned)lag <= 99u)
                        a0 = __fadd_rn(a0, sk[lag]);
                }
            }
            float a1 = 0.0f;
#pragma unroll 1
            for (int w = wlo; w <= c; ++w) {
                unsigned mm = W1[w];
                const int base = w << 5;
                while (mm) {
                    const int i = __ffs(mm) - 1;
                    mm &= mm - 1;
                    const int lag = t - (base + i);
                    if ((unsigned)lag <= 99u)
                        a1 = __fadd_rn(a1, sk[LL + lag]);
                }
            }
            stile[lane * 33 + j] = __fadd_rn(a0, a1);
        }
        __syncthreads();
#pragma unroll
        for (int r = 0; r < 4; ++r) {
            const int e = tid + r * 256;
            g_vmem[gbase + (size_t)c * 1024 + e] = stile[(e >> 5) * 33 + (e & 31)];
        }
        __syncthreads();
    }
}

// ---------------------------------------------------------------------------
// Phase 2: dense branch-free refractory scan (R8, proven). Only change: the
// g_vmem load is explicitly software-pipelined one step ahead so its DRAM
// latency hides behind the 99-lag fold instead of sitting on the critical
// path. Numerics untouched.
// ---------------------------------------------------------------------------
#define SCAN_SMEM (SLOTS * 128 * 4 + 128 * 4)

__global__ __launch_bounds__(128) void snn_scan_kernel(
    const float* __restrict__ refk,     // (L,)
    float* __restrict__ out)            // (T, B, N)
{
    extern __shared__ float dyn[];
    float* fV = dyn;                       // [SLOTS][128]
    float* sv = dyn + SLOTS * 128;         // [LL]

    const int tid = threadIdx.x;
    for (int i = tid; i < LL; i += 128) sv[i] = refk[i];
#pragma unroll
    for (int s = 0; s < SLOTS; ++s) fV[(s << 7) + tid] = 0.0f;
    __syncthreads();

    const int bn = blockIdx.x * 128 + tid;
    const float* pv = g_vmem + ((size_t)(bn >> 5)) * (32 * TT) + (bn & 31);
    float* po = out + bn;

    float v = __ldg(pv);                   // prefetch t = 0

#pragma unroll 1
    for (int t = 0; t < TT; ++t) {
        // prefetch next step's vmem early (hidden behind the fold)
        const float vnext = (t + 1 < TT) ? __ldg(pv + (size_t)(t + 1) * 32) : 0.0f;

        const int s0 = (t + 29) & 127;     // slot of te = t-99
        const int jw = 128 - s0;           // first j that wraps
        const float* colA = fV + ((s0 << 7) + tid);
        const float* colB = colA - (SLOTS << 7);

        float racc = 0.0f;
#pragma unroll
        for (int j = 0; j < 98; j += 2) {
            const int d = 99 - j;
            const float2 s2 = *(const float2*)(sv + (d - 1));  // (sr[d-1], sr[d])
            const float* p0 = (j < jw) ? colA : colB;
            const float* p1 = (j + 1 < jw) ? colA : colB;
            const float v0 = p0[j << 7];
            const float v1 = p1[(j + 1) << 7];
            racc = __fsub_rn(racc, __fmul_rn(v0, s2.y));
            racc = __fsub_rn(racc, __fmul_rn(v1, s2.x));
        }
        {   // j = 98, d = 1
            const float* p = (98 < jw) ? colA : colB;
            racc = __fsub_rn(racc, __fmul_rn(p[98 << 7], sv[1]));
        }

        const float veff = __fadd_rn(v, racc);
        const float nsp = floorf(fmaxf(veff, 0.0f));

        const float ad = fabsf(__fsub_rn(veff, 1.0f));
        const float sg = __fmul_rn(2.0f, expf(__fmul_rn(ad, -2.0f)));
        const float term = __fmul_rn(sg, veff);
        const float nadj = __fadd_rn(__fsub_rn(nsp, term), term);

        // unconditional push (silent steps store exact +0.0)
        fV[((t & 127) << 7) + tid] = nadj;

        po[(size_t)t * BN] = nadj;
        v = vnext;
    }
}

extern "C" void kernel_launch(void* const* d_in, const int* in_sizes, int n_in,
                              void* d_out, int out_size) {
    const float* spikes = (const float*)d_in[0];   // (T,B,S,N) float32
    const float* eps    = (const float*)d_in[1];   // (2,100)   float32
    const float* refk   = (const float*)d_in[2];   // (100,)    float32
    float* out = (float*)d_out;                    // (T,B,N)   float32

    cudaFuncSetAttribute(snn_scan_kernel,
                         cudaFuncAttributeMaxDynamicSharedMemorySize, SCAN_SMEM);

    snn_epsp_kernel<<<BN / 32, 256>>>(spikes, eps);
    snn_scan_kernel<<<BN / 128, 128, SCAN_SMEM>>>(refk, out);
}

// round 14
// speedup vs baseline: 1.0656x; 1.0656x over previous
#include <cuda_runtime.h>
#include <math.h>

#define TT 1024
#define BB 16
#define SS 2
#define NN 2048
#define BN (BB * NN)     // 32768
#define LL 100
#define SLOTS 128

// vmem scratch, TILED layout: [group = bn/32][t][bn%32]  (coalesced for scan)
__device__ float g_vmem[(size_t)BN * TT];

// ---------------------------------------------------------------------------
// Phase 1: EPSP conv. Bit-exact fold (ascending spike time, per synapse, then
// v = a0 + a1). Warp-ballot transpose (bit-identical sW, ~2x cheaper stage).
// ---------------------------------------------------------------------------
__global__ __launch_bounds__(256) void snn_epsp_kernel(
    const float* __restrict__ spikes,   // (T, B, S, N)
    const float* __restrict__ eps)      // (S, L)
{
    __shared__ unsigned smasks[2 * TT];     // [s*TT + t], bit i = neuron n0+i
    __shared__ unsigned sW[2 * 32 * 32];    // [s*1024 + j*32 + w], bit i = t=w*32+i
    __shared__ float sk[2 * LL];
    __shared__ float stile[32 * 33];

    const int tid = threadIdx.x;
    const int warpId = tid >> 5;
    const int lane = tid & 31;
    const int b  = blockIdx.x >> 6;
    const int n0 = (blockIdx.x & 63) * 32;

    for (int i = tid; i < 2 * LL; i += 256) sk[i] = eps[i];

    // ballot spikes -> per-(s,t) neuron masks (coalesced loads)
    for (int idx = warpId; idx < 2 * TT; idx += 8) {
        const int s = idx >> 10;
        const int t = idx & (TT - 1);
        const float val = spikes[(((size_t)t * BB + b) * SS + s) * NN + n0 + lane];
        const unsigned m = __ballot_sync(0xFFFFFFFFu, val != 0.0f);
        if (lane == 0) smasks[s * TT + t] = m;
    }
    __syncthreads();

    // warp-ballot bit-transpose: tile = (s, w) of 32 times x 32 neurons
    for (int tile = warpId; tile < 64; tile += 8) {
        const int s = tile >> 5;
        const int w = tile & 31;
        const unsigned m = smasks[s * TT + w * 32 + lane];  // times w*32+lane
#pragma unroll
        for (int j = 0; j < 32; ++j) {
            const unsigned bjt = __ballot_sync(0xFFFFFFFFu, (m >> j) & 1u);
            if (lane == j) sW[s * 1024 + j * 32 + w] = bjt;
        }
    }
    __syncthreads();

    const size_t gbase = (size_t)blockIdx.x * (32 * TT);

#pragma unroll 1
    for (int c = 0; c < 32; ++c) {
        const int t = c * 32 + lane;
        const int wlo = (c * 32 >= 99) ? ((c * 32 - 99) >> 5) : 0;

#pragma unroll 1
        for (int jj = 0; jj < 4; ++jj) {
            const int j = warpId + jj * 8;
            const unsigned* W0 = &sW[j * 32];
            const unsigned* W1 = &sW[1024 + j * 32];

            float a0 = 0.0f;
#pragma unroll 1
            for (int w = wlo; w <= c; ++w) {
                unsigned mm = W0[w];                 // warp-uniform
                const int base = w << 5;
                while (mm) {
                    const int i = __ffs(mm) - 1;
                    mm &= mm - 1;
                    const int lag = t - (base + i);  // per-lane
                    if ((unsigned)lag <= 99u)
                        a0 = __fadd_rn(a0, sk[lag]);
                }
            }
            float a1 = 0.0f;
#pragma unroll 1
            for (int w = wlo; w <= c; ++w) {
                unsigned mm = W1[w];
                const int base = w << 5;
                while (mm) {
                    const int i = __ffs(mm) - 1;
                    mm &= mm - 1;
                    const int lag = t - (base + i);
                    if ((unsigned)lag <= 99u)
                        a1 = __fadd_rn(a1, sk[LL + lag]);
                }
            }
            stile[lane * 33 + j] = __fadd_rn(a0, a1);
        }
        __syncthreads();
#pragma unroll
        for (int r = 0; r < 4; ++r) {
            const int e = tid + r * 256;
            g_vmem[gbase + (size_t)c * 1024 + e] = stile[(e >> 5) * 33 + (e & 31)];
        }
        __syncthreads();
    }
}

// ---------------------------------------------------------------------------
// Phase 2: dense branch-free refractory scan. Exact R8 structure (no
// prefetch), with the sr table EXPLICITLY hoisted into registers before the
// t-loop — pinning the 125-reg schedule R8's compiler found on its own.
// Numerics identical: same fold order (d = 99..1), mul-then-add rounding.
// ---------------------------------------------------------------------------
#define SCAN_SMEM (SLOTS * 128 * 4 + 128 * 4)

__global__ __launch_bounds__(128) void snn_scan_kernel(
    const float* __restrict__ refk,     // (L,)
    float* __restrict__ out)            // (T, B, N)
{
    extern __shared__ float dyn[];
    float* fV = dyn;                       // [SLOTS][128]
    float* sv = dyn + SLOTS * 128;         // [LL]

    const int tid = threadIdx.x;
    for (int i = tid; i < LL; i += 128) sv[i] = refk[i];
#pragma unroll
    for (int s = 0; s < SLOTS; ++s) fV[(s << 7) + tid] = 0.0f;
    __syncthreads();

    // hoist sr into registers: srr[j] = sr[99 - j]  (lag used at fold step j)
    float srr[99];
#pragma unroll
    for (int j = 0; j < 99; ++j) srr[j] = sv[99 - j];

    const int bn = blockIdx.x * 128 + tid;
    const float* pv = g_vmem + ((size_t)(bn >> 5)) * (32 * TT) + (bn & 31);
    float* po = out + bn;

#pragma unroll 1
    for (int t = 0; t < TT; ++t) {
        const float v = pv[(size_t)t * 32];          // coalesced

        const int s0 = (t + 29) & 127;               // slot of te = t-99
        const int jw = 128 - s0;                     // first j that wraps
        const float* colA = fV + ((s0 << 7) + tid);
        const float* colB = colA - (SLOTS << 7);

        float racc = 0.0f;
#pragma unroll
        for (int j = 0; j < 99; ++j) {
            const float* p = (j < jw) ? colA : colB;
            const float vj = p[j << 7];
            racc = __fsub_rn(racc, __fmul_rn(vj, srr[j]));
        }

        const float veff = __fadd_rn(v, racc);
        const float nsp = floorf(fmaxf(veff, 0.0f));

        const float ad = fabsf(__fsub_rn(veff, 1.0f));
        const float sg = __fmul_rn(2.0f, expf(__fmul_rn(ad, -2.0f)));
        const float term = __fmul_rn(sg, veff);
        const float nadj = __fadd_rn(__fsub_rn(nsp, term), term);

        // unconditional push (silent steps store exact +0.0)
        fV[((t & 127) << 7) + tid] = nadj;

        po[(size_t)t * BN] = nadj;
    }
}

extern "C" void kernel_launch(void* const* d_in, const int* in_sizes, int n_in,
                              void* d_out, int out_size) {
    const float* spikes = (const float*)d_in[0];   // (T,B,S,N) float32
    const float* eps    = (const float*)d_in[1];   // (2,100)   float32
    const float* refk   = (const float*)d_in[2];   // (100,)    float32
    float* out = (float*)d_out;                    // (T,B,N)   float32

    cudaFuncSetAttribute(snn_scan_kernel,
                         cudaFuncAttributeMaxDynamicSharedMemorySize, SCAN_SMEM);

    snn_epsp_kernel<<<BN / 32, 256>>>(spikes, eps);
    snn_scan_kernel<<<BN / 128, 128, SCAN_SMEM>>>(refk, out);
}

// round 17
// speedup vs baseline: 1.5197x; 1.4262x over previous
#include <cuda_runtime.h>
#include <math.h>

#define TT 1024
#define BB 16
#define SS 2
#define NN 2048
#define BN (BB * NN)     // 32768
#define LL 100
#define SLOTS 128

// vmem scratch, TILED layout: [group = bn/32][t][bn%32]  (coalesced for scan)
__device__ float g_vmem[(size_t)BN * TT];

// ---------------------------------------------------------------------------
// Phase 1: EPSP conv. Bit-exact fold (ascending spike time, per synapse, then
// v = a0 + a1). Ballot transpose; spike-load loop unrolled for MLP.
// ---------------------------------------------------------------------------
__global__ __launch_bounds__(256) void snn_epsp_kernel(
    const float* __restrict__ spikes,   // (T, B, S, N)
    const float* __restrict__ eps)      // (S, L)
{
    __shared__ unsigned smasks[2 * TT];     // [s*TT + t], bit i = neuron n0+i
    __shared__ unsigned sW[2 * 32 * 32];    // [s*1024 + j*32 + w], bit i = t=w*32+i
    __shared__ float sk[2 * LL];
    __shared__ float stile[32 * 33];

    const int tid = threadIdx.x;
    const int warpId = tid >> 5;
    const int lane = tid & 31;
    const int b  = blockIdx.x >> 6;
    const int n0 = (blockIdx.x & 63) * 32;

    for (int i = tid; i < 2 * LL; i += 256) sk[i] = eps[i];

    // ballot spikes -> per-(s,t) neuron masks; unrolled for load MLP
#pragma unroll 8
    for (int idx = warpId; idx < 2 * TT; idx += 8) {
        const int s = idx >> 10;
        const int t = idx & (TT - 1);
        const float val = spikes[(((size_t)t * BB + b) * SS + s) * NN + n0 + lane];
        const unsigned m = __ballot_sync(0xFFFFFFFFu, val != 0.0f);
        if (lane == 0) smasks[s * TT + t] = m;
    }
    __syncthreads();

    // warp-ballot bit-transpose: tile = (s, w) of 32 times x 32 neurons
    for (int tile = warpId; tile < 64; tile += 8) {
        const int s = tile >> 5;
        const int w = tile & 31;
        const unsigned m = smasks[s * TT + w * 32 + lane];
#pragma unroll
        for (int j = 0; j < 32; ++j) {
            const unsigned bjt = __ballot_sync(0xFFFFFFFFu, (m >> j) & 1u);
            if (lane == j) sW[s * 1024 + j * 32 + w] = bjt;
        }
    }
    __syncthreads();

    const size_t gbase = (size_t)blockIdx.x * (32 * TT);

#pragma unroll 1
    for (int c = 0; c < 32; ++c) {
        const int t = c * 32 + lane;
        const int wlo = (c * 32 >= 99) ? ((c * 32 - 99) >> 5) : 0;

#pragma unroll 1
        for (int jj = 0; jj < 4; ++jj) {
            const int j = warpId + jj * 8;
            const unsigned* W0 = &sW[j * 32];
            const unsigned* W1 = &sW[1024 + j * 32];

            float a0 = 0.0f;
#pragma unroll 1
            for (int w = wlo; w <= c; ++w) {
                unsigned mm = W0[w];                 // warp-uniform
                const int base = w << 5;
                while (mm) {
                    const int i = __ffs(mm) - 1;
                    mm &= mm - 1;
                    const int lag = t - (base + i);
                    if ((unsigned)lag <= 99u)
                        a0 = __fadd_rn(a0, sk[lag]);
                }
            }
            float a1 = 0.0f;
#pragma unroll 1
            for (int w = wlo; w <= c; ++w) {
                unsigned mm = W1[w];
                const int base = w << 5;
                while (mm) {
                    const int i = __ffs(mm) - 1;
                    mm &= mm - 1;
                    const int lag = t - (base + i);
                    if ((unsigned)lag <= 99u)
                        a1 = __fadd_rn(a1, sk[LL + lag]);
                }
            }
            stile[lane * 33 + j] = __fadd_rn(a0, a1);
        }
        __syncthreads();
#pragma unroll
        for (int r = 0; r < 4; ++r) {
            const int e = tid + r * 256;
            g_vmem[gbase + (size_t)c * 1024 + e] = stile[(e >> 5) * 33 + (e & 31)];
        }
        __syncthreads();
    }
}

// ---------------------------------------------------------------------------
// Phase 2: dense refractory scan, 4-step temporal blocking.
// Steps t0..t0+3 share the fV loads (one LDS per te serves 4 accumulators).
// Each racc_k accumulates __fsub_rn(racc, __fmul_rn(val, sr[d])) over te
// STRICTLY ASCENDING (smem te = t0-99..t0-1 in the j-loop, then in-block
// spikes te = t0..t0+2 appended last) — the exact op sequence of the
// reference fold. Zero values contribute exact +0.0 (identity). d > 99
// exclusions are compile-time. 4 independent FSUB chains hide latency.
// ---------------------------------------------------------------------------
#define SCAN_SMEM (SLOTS * 128 * 4 + 128 * 4)

__global__ __launch_bounds__(128) void snn_scan_kernel(
    const float* __restrict__ refk,     // (L,)
    float* __restrict__ out)            // (T, B, N)
{
    extern __shared__ float dyn[];
    float* fV = dyn;                       // [SLOTS][128]
    float* sv = dyn + SLOTS * 128;         // [LL]

    const int tid = threadIdx.x;
    for (int i = tid; i < LL; i += 128) sv[i] = refk[i];
#pragma unroll
    for (int s = 0; s < SLOTS; ++s) fV[(s << 7) + tid] = 0.0f;
    __syncthreads();

    // srd[d] = refractory coefficient for lag d (register-resident)
    float srd[LL];
#pragma unroll
    for (int d = 1; d < LL; ++d) srd[d] = sv[d];

    const int bn = blockIdx.x * 128 + tid;
    const float* pv = g_vmem + ((size_t)(bn >> 5)) * (32 * TT) + (bn & 31);
    float* po = out + bn;

#pragma unroll 1
    for (int t0 = 0; t0 < TT; t0 += 4) {
        const float v0 = pv[(size_t)(t0 + 0) * 32];
        const float v1 = pv[(size_t)(t0 + 1) * 32];
        const float v2 = pv[(size_t)(t0 + 2) * 32];
        const float v3 = pv[(size_t)(t0 + 3) * 32];

        const int s0 = (t0 + 29) & 127;              // slot of te = t0-99
        const int jw = 128 - s0;                     // first j that wraps
        const float* colA = fV + ((s0 << 7) + tid);
        const float* colB = colA - (SLOTS << 7);

        float r0 = 0.0f, r1 = 0.0f, r2 = 0.0f, r3 = 0.0f;
#pragma unroll
        for (int j = 0; j < 99; ++j) {               // te = t0-99+j, ascending
            const float* p = (j < jw) ? colA : colB;
            const float val = p[j << 7];
            /* d for step t0+k is (99+k)-j; include only d <= 99 */
            r0 = __fsub_rn(r0, __fmul_rn(val, srd[99 - j]));
            if (j >= 1) r1 = __fsub_rn(r1, __fmul_rn(val, srd[100 - j]));
            if (j >= 2) r2 = __fsub_rn(r2, __fmul_rn(val, srd[101 - j]));
            if (j >= 3) r3 = __fsub_rn(r3, __fmul_rn(val, srd[102 - j]));
        }

        // ---- step t0 ----
        float veff = __fadd_rn(v0, r0);
        float nsp  = floorf(fmaxf(veff, 0.0f));
        float ad   = fabsf(__fsub_rn(veff, 1.0f));
        float sg   = __fmul_rn(2.0f, expf(__fmul_rn(ad, -2.0f)));
        float term = __fmul_rn(sg, veff);
        const float n0v = __fadd_rn(__fsub_rn(nsp, term), term);

        // ---- step t0+1 (append te = t0, still ascending) ----
        r1 = __fsub_rn(r1, __fmul_rn(n0v, srd[1]));
        veff = __fadd_rn(v1, r1);
        nsp  = floorf(fmaxf(veff, 0.0f));
        ad   = fabsf(__fsub_rn(veff, 1.0f));
        sg   = __fmul_rn(2.0f, expf(__fmul_rn(ad, -2.0f)));
        term = __fmul_rn(sg, veff);
        const float n1v = __fadd_rn(__fsub_rn(nsp, term), term);

        // ---- step t0+2 ----
        r2 = __fsub_rn(r2, __fmul_rn(n0v, srd[2]));
        r2 = __fsub_rn(r2, __fmul_rn(n1v, srd[1]));
        veff = __fadd_rn(v2, r2);
        nsp  = floorf(fmaxf(veff, 0.0f));
        ad   = fabsf(__fsub_rn(veff, 1.0f));
        sg   = __fmul_rn(2.0f, expf(__fmul_rn(ad, -2.0f)));
        term = __fmul_rn(sg, veff);
        const float n2v = __fadd_rn(__fsub_rn(nsp, term), term);

        // ---- step t0+3 ----
        r3 = __fsub_rn(r3, __fmul_rn(n0v, srd[3]));
        r3 = __fsub_rn(r3, __fmul_rn(n1v, srd[2]));
        r3 = __fsub_rn(r3, __fmul_rn(n2v, srd[1]));
        veff = __fadd_rn(v3, r3);
        nsp  = floorf(fmaxf(veff, 0.0f));
        ad   = fabsf(__fsub_rn(veff, 1.0f));
        sg   = __fmul_rn(2.0f, expf(__fmul_rn(ad, -2.0f)));
        term = __fmul_rn(sg, veff);
        const float n3v = __fadd_rn(__fsub_rn(nsp, term), term);

        // push all 4 (t0 % 4 == 0 -> no wrap within the quartet)
        const int ws = (t0 & 127) << 7;
        fV[ws + tid]             = n0v;
        fV[ws + (1 << 7) + tid]  = n1v;
        fV[ws + (2 << 7) + tid]  = n2v;
        fV[ws + (3 << 7) + tid]  = n3v;

        po[(size_t)(t0 + 0) * BN] = n0v;
        po[(size_t)(t0 + 1) * BN] = n1v;
        po[(size_t)(t0 + 2) * BN] = n2v;
        po[(size_t)(t0 + 3) * BN] = n3v;
    }
}

extern "C" void kernel_launch(void* const* d_in, const int* in_sizes, int n_in,
                              void* d_out, int out_size) {
    const float* spikes = (const float*)d_in[0];   // (T,B,S,N) float32
    const float* eps    = (const float*)d_in[1];   // (2,100)   float32
    const float* refk   = (const float*)d_in[2];   // (100,)    float32
    float* out = (float*)d_out;                    // (T,B,N)   float32

    cudaFuncSetAttribute(snn_scan_kernel,
                         cudaFuncAttributeMaxDynamicSharedMemorySize, SCAN_SMEM);

    snn_epsp_kernel<<<BN / 32, 256>>>(spikes, eps);
    snn_scan_kernel<<<BN / 128, 128, SCAN_SMEM>>>(refk, out);
}